// round 8
// baseline (speedup 1.0000x reference)
#include <cuda_runtime.h>
#include <cstdint>

// ---------------- problem constants ----------------
#define VN     512          // graph nodes
#define LN     13           // sequence length
#define BB     64           // batch
#define CN     32           // in channels
#define NC     (BB*CN)      // 2048
#define MCOLS  (NC*LN)      // 26624  (= 208 * 128, exact)
#define CO     64           // out channels
#define CCAT   224          // 7*CN
#define KDIM   VN           // contraction dim of propagation
#define NM     425984       // B*V*L = 64*512*13  (epilogue N; = 1664*256)
#define VLN    6656         // V*L = 512*13  (= 26*256)

// GEMM tiling (propagation)
#define BM  128
#define BNT 128
#define BK  16

// scratch
__device__ float g_Xt[(size_t)VN * MCOLS];        // x transposed: [v][(n,c,l)]
__device__ float g_H [(size_t)CCAT * NM];         // concat buffer: [j*32+c][(n,v,l)]
__device__ float g_S2[3 * (size_t)VN * VN];       // squared supports A*A

// ---------------- packed f32x2 helpers (Blackwell FFMA2 path) ----------------
__device__ __forceinline__ unsigned long long pack_dup(float b) {
    unsigned long long r;
    asm("mov.b64 %0, {%1, %1};" : "=l"(r) : "f"(b));
    return r;
}
__device__ __forceinline__ void fma2(unsigned long long &d,
                                     unsigned long long a,
                                     unsigned long long b) {
    asm("fma.rn.f32x2 %0, %1, %2, %0;" : "+l"(d) : "l"(a), "l"(b));
}
__device__ __forceinline__ float lo32(unsigned long long v) {
    return __uint_as_float((unsigned)(v & 0xffffffffull));
}
__device__ __forceinline__ float hi32(unsigned long long v) {
    return __uint_as_float((unsigned)(v >> 32));
}

// ---------------- 1) transpose x[n,c,v,l] -> Xt[v][(n,c,l)]  + H rows 0..31 --
__global__ void transpose_kernel(const float* __restrict__ x) {
    int v  = blockIdx.x;
    int nc = blockIdx.y * blockDim.x + threadIdx.x;
    int n  = nc >> 5;
    int c  = nc & 31;
    const float* src = x + (size_t)nc * (VN * LN) + v * LN;
    float* dst1 = g_Xt + (size_t)v * MCOLS + nc * LN;
    float* dst2 = g_H  + (size_t)c * NM + (size_t)n * VLN + v * LN;
#pragma unroll
    for (int l = 0; l < LN; ++l) {
        float val = src[l];
        dst1[l] = val;
        dst2[l] = val;
    }
}

// ---------------- 1b) square supports: S2 = A * A  (512x512x512, tiny) ------
__global__ void __launch_bounds__(256) square_support(
    const float* __restrict__ A0, const float* __restrict__ A1,
    const float* __restrict__ A2)
{
    const int z = blockIdx.z;
    const float* __restrict__ A = (z == 0) ? A0 : ((z == 1) ? A1 : A2);
    float* __restrict__ C = g_S2 + (size_t)z * VN * VN;

    const int i0 = blockIdx.y * 64;
    const int j0 = blockIdx.x * 64;

    __shared__ __align__(16) float As[64][16];
    __shared__ __align__(16) float Bs[16][64];

    const int tid = threadIdx.x;
    const int ty = tid >> 4;    // 0..15 -> i
    const int tx = tid & 15;    // 0..15 -> j
    const int ar = tid >> 2;    // 0..63
    const int ac = (tid & 3) * 4;
    const int br = tid >> 4;    // 0..15
    const int bc = (tid & 15) * 4;

    float acc[4][4];
#pragma unroll
    for (int i = 0; i < 4; ++i)
#pragma unroll
        for (int j = 0; j < 4; ++j) acc[i][j] = 0.f;

    for (int k0 = 0; k0 < VN; k0 += 16) {
        float4 av = *(const float4*)(A + (size_t)(i0 + ar) * VN + k0 + ac);
        float4 bv = *(const float4*)(A + (size_t)(k0 + br) * VN + j0 + bc);
        __syncthreads();
        *(float4*)&As[ar][ac] = av;
        *(float4*)&Bs[br][bc] = bv;
        __syncthreads();
#pragma unroll
        for (int k = 0; k < 16; ++k) {
            float a0 = As[ty * 4 + 0][k], a1 = As[ty * 4 + 1][k];
            float a2 = As[ty * 4 + 2][k], a3 = As[ty * 4 + 3][k];
            float4 b = *(const float4*)&Bs[k][tx * 4];
            acc[0][0] += a0 * b.x; acc[0][1] += a0 * b.y; acc[0][2] += a0 * b.z; acc[0][3] += a0 * b.w;
            acc[1][0] += a1 * b.x; acc[1][1] += a1 * b.y; acc[1][2] += a1 * b.z; acc[1][3] += a1 * b.w;
            acc[2][0] += a2 * b.x; acc[2][1] += a2 * b.y; acc[2][2] += a2 * b.z; acc[2][3] += a2 * b.w;
            acc[3][0] += a3 * b.x; acc[3][1] += a3 * b.y; acc[3][2] += a3 * b.z; acc[3][3] += a3 * b.w;
        }
    }
#pragma unroll
    for (int i = 0; i < 4; ++i) {
        float4 v = make_float4(acc[i][0], acc[i][1], acc[i][2], acc[i][3]);
        *(float4*)(C + (size_t)(i0 + ty * 4 + i) * VN + j0 + tx * 4) = v;
    }
}

// ---------------- 2) propagation SGEMM -> scatter into g_H ------------------
// C[w,m] = sum_v A[v,w] * Xt[v,m]; m = n*416 + c*13 + l.
// z = 0..2: A = support_z (order 1, concat block j = 1+2z)
// z = 3..5: A = S2_{z-3}  (order 2, concat block j = 2+2(z-3))
// Output element -> g_H[(j*32+c)*NM + n*6656 + w*13 + l]
__global__ void __launch_bounds__(256) prop_gemm(
    const float* __restrict__ A0, const float* __restrict__ A1,
    const float* __restrict__ A2)
{
    const int z = blockIdx.z;
    const float* __restrict__ A =
        (z == 0) ? A0 : (z == 1) ? A1 : (z == 2) ? A2
                  : (g_S2 + (size_t)(z - 3) * VN * VN);
    const int j = (z < 3) ? (1 + 2 * z) : (2 + 2 * (z - 3));
    const float* __restrict__ Bm = g_Xt;

    const int w0 = blockIdx.y * BM;
    const int m0 = blockIdx.x * BNT;

    __shared__ __align__(16) float As[2][BK][BM];
    __shared__ __align__(16) float Bs[2][BK][BNT];

    const int tid = threadIdx.x;
    const int lk = tid >> 5;   // 0..7
    const int lq = tid & 31;   // 0..31
    const int ty = tid >> 4;   // 0..15 (w)
    const int tx = tid & 15;   // 0..15 (m)

    const float* Ag = A  + (size_t)lk * VN    + w0 + lq * 4;
    const float* Bg = Bm + (size_t)lk * MCOLS + m0 + lq * 4;

    unsigned long long acc[4][8];
#pragma unroll
    for (int i = 0; i < 4; ++i)
#pragma unroll
        for (int jj = 0; jj < 8; ++jj) acc[i][jj] = 0ull;

    // prologue: chunk 0 -> buffer 0
    {
        float4 a0 = *(const float4*)Ag;
        float4 a1 = *(const float4*)(Ag + 8 * VN);
        float4 b0 = *(const float4*)Bg;
        float4 b1 = *(const float4*)(Bg + 8 * MCOLS);
        *(float4*)&As[0][lk    ][lq * 4] = a0;
        *(float4*)&As[0][lk + 8][lq * 4] = a1;
        *(float4*)&Bs[0][lk    ][lq * 4] = b0;
        *(float4*)&Bs[0][lk + 8][lq * 4] = b1;
    }
    __syncthreads();

    int buf = 0;
#pragma unroll 1
    for (int kt = 0; kt < KDIM / BK; ++kt) {
        float4 na0, na1, nb0, nb1;
        const bool has_next = (kt < KDIM / BK - 1);
        if (has_next) {
            const float* Ap = Ag + (size_t)(kt + 1) * (BK * VN);
            const float* Bp = Bg + (size_t)(kt + 1) * (BK * MCOLS);
            na0 = *(const float4*)Ap;
            na1 = *(const float4*)(Ap + 8 * VN);
            nb0 = *(const float4*)Bp;
            nb1 = *(const float4*)(Bp + 8 * MCOLS);
        }
#pragma unroll
        for (int kk = 0; kk < BK; ++kk) {
            ulonglong2 alo = *(const ulonglong2*)&As[buf][kk][ty * 4];
            ulonglong2 ahi = *(const ulonglong2*)&As[buf][kk][64 + ty * 4];
            float4 blo = *(const float4*)&Bs[buf][kk][tx * 4];
            float4 bhi = *(const float4*)&Bs[buf][kk][64 + tx * 4];
            unsigned long long av[4] = {alo.x, alo.y, ahi.x, ahi.y};
            unsigned long long bb[8];
            bb[0] = pack_dup(blo.x); bb[1] = pack_dup(blo.y);
            bb[2] = pack_dup(blo.z); bb[3] = pack_dup(blo.w);
            bb[4] = pack_dup(bhi.x); bb[5] = pack_dup(bhi.y);
            bb[6] = pack_dup(bhi.z); bb[7] = pack_dup(bhi.w);
#pragma unroll
            for (int i = 0; i < 4; ++i)
#pragma unroll
                for (int jj = 0; jj < 8; ++jj)
                    fma2(acc[i][jj], av[i], bb[jj]);
        }
        if (has_next) {
            int nb = buf ^ 1;
            *(float4*)&As[nb][lk    ][lq * 4] = na0;
            *(float4*)&As[nb][lk + 8][lq * 4] = na1;
            *(float4*)&Bs[nb][lk    ][lq * 4] = nb0;
            *(float4*)&Bs[nb][lk + 8][lq * 4] = nb1;
        }
        __syncthreads();
        buf ^= 1;
    }

    // scatter epilogue into g_H: row = j*32 + c, col = n*6656 + w*13 + l
    const int jbase = j * CN;
    size_t coloff[8];
#pragma unroll
    for (int jj = 0; jj < 8; ++jj) {
        int mcol = m0 + ((jj >> 2) * 64) + tx * 4 + (jj & 3);
        int n = mcol / 416;
        int r = mcol - n * 416;
        int c = r / 13;
        int l = r - c * 13;
        coloff[jj] = (size_t)(jbase + c) * NM + (size_t)n * VLN + l;
    }
#pragma unroll
    for (int ia = 0; ia < 4; ++ia) {
        int w = w0 + ((ia >= 2) ? 64 : 0) + ty * 4 + (ia & 1) * 2;
        size_t wo = (size_t)w * 13;
#pragma unroll
        for (int jj = 0; jj < 8; ++jj) {
            g_H[coloff[jj] + wo]      = lo32(acc[ia][jj]);
            g_H[coloff[jj] + wo + 13] = hi32(acc[ia][jj]);
        }
    }
}

// ---------------- 3) epilogue skinny GEMM: out = W * H + b ------------------
// out[o, m] (o=64, m=(n,v,l)=425984), K = 224. Tile 64 x 256, 256 threads,
// 8x8 per thread, double-buffered, fma.rn.f32x2 inner loop.
#define EBK 8
__global__ void __launch_bounds__(256) mix_gemm(
    const float* __restrict__ Wm, const float* __restrict__ bias,
    float* __restrict__ out)
{
    const int m0 = blockIdx.x * 256;

    __shared__ __align__(16) float Ws[2][EBK][CO];
    __shared__ __align__(16) float Bs[2][EBK][256];

    const int tid = threadIdx.x;
    const int ty = tid >> 5;    // 0..7  (o)
    const int tx = tid & 31;    // 0..31 (m)
    const int lr = tid >> 5;    // Bs load row 0..7
    const int lc = (tid & 31) * 4;
    const int wo_ = tid & 63;   // Ws load: o
    const int wk_ = tid >> 6;   // Ws load: kk (0..3; +4 for second)

    unsigned long long acc[4][8];
#pragma unroll
    for (int i = 0; i < 4; ++i)
#pragma unroll
        for (int jj = 0; jj < 8; ++jj) acc[i][jj] = 0ull;

    // prologue: chunk 0
    {
        float4 b0 = *(const float4*)(g_H + (size_t)lr * NM + m0 + lc);
        float4 b1 = *(const float4*)(g_H + (size_t)lr * NM + m0 + lc + 128);
        float w0v = Wm[wo_ * CCAT + wk_];
        float w1v = Wm[wo_ * CCAT + wk_ + 4];
        *(float4*)&Bs[0][lr][lc]       = b0;
        *(float4*)&Bs[0][lr][lc + 128] = b1;
        Ws[0][wk_][wo_]     = w0v;
        Ws[0][wk_ + 4][wo_] = w1v;
    }
    __syncthreads();

    int buf = 0;
#pragma unroll 1
    for (int kt = 0; kt < CCAT / EBK; ++kt) {
        float4 nb0, nb1;
        float nw0, nw1;
        const bool has_next = (kt < CCAT / EBK - 1);
        if (has_next) {
            int k0 = (kt + 1) * EBK;
            nb0 = *(const float4*)(g_H + (size_t)(k0 + lr) * NM + m0 + lc);
            nb1 = *(const float4*)(g_H + (size_t)(k0 + lr) * NM + m0 + lc + 128);
            nw0 = Wm[wo_ * CCAT + k0 + wk_];
            nw1 = Wm[wo_ * CCAT + k0 + wk_ + 4];
        }
#pragma unroll
        for (int kk = 0; kk < EBK; ++kk) {
            ulonglong2 a01 = *(const ulonglong2*)&Ws[buf][kk][ty * 4];
            ulonglong2 a23 = *(const ulonglong2*)&Ws[buf][kk][32 + ty * 4];
            float4 blo = *(const float4*)&Bs[buf][kk][tx * 4];
            float4 bhi = *(const float4*)&Bs[buf][kk][128 + tx * 4];
            unsigned long long av[4] = {a01.x, a01.y, a23.x, a23.y};
            unsigned long long bb[8];
            bb[0] = pack_dup(blo.x); bb[1] = pack_dup(blo.y);
            bb[2] = pack_dup(blo.z); bb[3] = pack_dup(blo.w);
            bb[4] = pack_dup(bhi.x); bb[5] = pack_dup(bhi.y);
            bb[6] = pack_dup(bhi.z); bb[7] = pack_dup(bhi.w);
#pragma unroll
            for (int i = 0; i < 4; ++i)
#pragma unroll
                for (int jj = 0; jj < 8; ++jj)
                    fma2(acc[i][jj], av[i], bb[jj]);
        }
        if (has_next) {
            int nb = buf ^ 1;
            *(float4*)&Bs[nb][lr][lc]       = nb0;
            *(float4*)&Bs[nb][lr][lc + 128] = nb1;
            Ws[nb][wk_][wo_]     = nw0;
            Ws[nb][wk_ + 4][wo_] = nw1;
        }
        __syncthreads();
        buf ^= 1;
    }

    // write: m0 tile lies entirely within one n (6656 % 256 == 0)
    const int n   = m0 / VLN;
    const int vl0 = m0 - n * VLN;
#pragma unroll
    for (int ia = 0; ia < 4; ++ia) {
        int o0 = ((ia >= 2) ? 32 : 0) + ty * 4 + (ia & 1) * 2;
        float blo = bias[o0], bhi = bias[o0 + 1];
        float* plo = out + ((size_t)n * CO + o0) * VLN + vl0 + tx * 4;
        float* phi = plo + VLN;
        float4 vlo0 = make_float4(lo32(acc[ia][0]) + blo, lo32(acc[ia][1]) + blo,
                                  lo32(acc[ia][2]) + blo, lo32(acc[ia][3]) + blo);
        float4 vlo1 = make_float4(lo32(acc[ia][4]) + blo, lo32(acc[ia][5]) + blo,
                                  lo32(acc[ia][6]) + blo, lo32(acc[ia][7]) + blo);
        float4 vhi0 = make_float4(hi32(acc[ia][0]) + bhi, hi32(acc[ia][1]) + bhi,
                                  hi32(acc[ia][2]) + bhi, hi32(acc[ia][3]) + bhi);
        float4 vhi1 = make_float4(hi32(acc[ia][4]) + bhi, hi32(acc[ia][5]) + bhi,
                                  hi32(acc[ia][6]) + bhi, hi32(acc[ia][7]) + bhi);
        *(float4*)(plo)       = vlo0;
        *(float4*)(plo + 128) = vlo1;
        *(float4*)(phi)       = vhi0;
        *(float4*)(phi + 128) = vhi1;
    }
}

// ---------------- launch ----------------
extern "C" void kernel_launch(void* const* d_in, const int* in_sizes, int n_in,
                              void* d_out, int out_size) {
    (void)in_sizes; (void)n_in; (void)out_size;
    const float* x  = (const float*)d_in[0];
    const float* s0 = (const float*)d_in[1];
    const float* s1 = (const float*)d_in[2];
    const float* s2 = (const float*)d_in[3];
    const float* Wm = (const float*)d_in[4];
    const float* bb = (const float*)d_in[5];
    float* out = (float*)d_out;

    // 1) x -> Xt  and  H rows 0..31 (concat block 0)
    transpose_kernel<<<dim3(VN, NC / 128), 128>>>(x);
    // 1b) S2_s = A_s * A_s  (enables fully parallel order-2 propagation)
    square_support<<<dim3(VN / 64, VN / 64, 3), 256>>>(s0, s1, s2);
    // 2) all 6 propagations in ONE launch, scattered into H blocks 1..6
    prop_gemm<<<dim3(MCOLS / BNT, VN / BM, 6), 256>>>(s0, s1, s2);
    // 3) epilogue GEMM: out = W * H + b  (coalesced both sides)
    mix_gemm<<<dim3(NM / 256), 256>>>(Wm, bb, out);
}